// round 1
// baseline (speedup 1.0000x reference)
#include <cuda_runtime.h>
#include <cuda_bf16.h>
#include <math.h>

// Problem constants (from reference)
#define D_DIM   4096
#define E_DIM   64
#define TOPK    8
#define SCALE_F 5.0f
#define EPS_F   1e-12f

// GEMM tiling
#define BM 64
#define BK 16
#define TM 4
#define TN 4
// 256 threads: 16 (expert groups) x 16 (row groups)

__global__ __launch_bounds__(256, 2)
void router_gemm_kernel(const float* __restrict__ x,
                        const float* __restrict__ sig,
                        float* __restrict__ resonance,   // [N, 64], scaled
                        int n_rows)
{
    __shared__ float xs[BK][BM];     // transposed x tile
    __shared__ float ss[BK][E_DIM];  // transposed sig tile
    __shared__ float inv_norm_sh[BM];

    const int t   = threadIdx.x;
    const int tx  = t & 15;          // expert group (0..15) -> experts tx*4..+3
    const int ty  = t >> 4;          // row group    (0..15) -> rows    ty*4..+3
    const int row0 = blockIdx.x * BM;

    // loader coords: 256 threads load 64 rows x 16 cols (one float4 each)
    const int l_row = t >> 2;        // 0..63
    const int l_c4  = (t & 3) * 4;   // 0,4,8,12

    float acc[TM][TN];
#pragma unroll
    for (int i = 0; i < TM; i++)
#pragma unroll
        for (int j = 0; j < TN; j++) acc[i][j] = 0.f;

    float sumsq[TM] = {0.f, 0.f, 0.f, 0.f};

    const float* xg = x   + (size_t)(row0 + l_row) * D_DIM + l_c4;
    const float* sg = sig + (size_t)l_row          * D_DIM + l_c4;

    for (int k0 = 0; k0 < D_DIM; k0 += BK) {
        // load x tile (transposed into smem)
        float4 xv = *reinterpret_cast<const float4*>(xg + k0);
        float4 sv = *reinterpret_cast<const float4*>(sg + k0);
        xs[l_c4 + 0][l_row] = xv.x;
        xs[l_c4 + 1][l_row] = xv.y;
        xs[l_c4 + 2][l_row] = xv.z;
        xs[l_c4 + 3][l_row] = xv.w;
        ss[l_c4 + 0][l_row] = sv.x;
        ss[l_c4 + 1][l_row] = sv.y;
        ss[l_c4 + 2][l_row] = sv.z;
        ss[l_c4 + 3][l_row] = sv.w;
        __syncthreads();

#pragma unroll
        for (int k = 0; k < BK; k++) {
            float4 a = *reinterpret_cast<const float4*>(&xs[k][ty * TM]);
            float4 b = *reinterpret_cast<const float4*>(&ss[k][tx * TN]);
            float av[4] = {a.x, a.y, a.z, a.w};
            float bv[4] = {b.x, b.y, b.z, b.w};
#pragma unroll
            for (int i = 0; i < TM; i++)
#pragma unroll
                for (int j = 0; j < TN; j++)
                    acc[i][j] = fmaf(av[i], bv[j], acc[i][j]);
            if (tx == 0) {
#pragma unroll
                for (int i = 0; i < TM; i++)
                    sumsq[i] = fmaf(av[i], av[i], sumsq[i]);
            }
        }
        __syncthreads();
    }

    if (tx == 0) {
#pragma unroll
        for (int i = 0; i < TM; i++) {
            float nrm = fmaxf(sqrtf(sumsq[i]), EPS_F);
            inv_norm_sh[ty * TM + i] = 1.f / nrm;
        }
    }
    __syncthreads();

#pragma unroll
    for (int i = 0; i < TM; i++) {
        float s = SCALE_F * inv_norm_sh[ty * TM + i];
        float4 o;
        o.x = acc[i][0] * s;
        o.y = acc[i][1] * s;
        o.z = acc[i][2] * s;
        o.w = acc[i][3] * s;
        *reinterpret_cast<float4*>(
            &resonance[(size_t)(row0 + ty * TM + i) * E_DIM + tx * TN]) = o;
    }
}

__device__ __forceinline__ float softplus_f(float v) {
    // log(1+exp(v)) stable: max(v,0) + log1p(exp(-|v|))
    return fmaxf(v, 0.f) + log1pf(expf(-fabsf(v)));
}

// one warp per row: iterative top-8 of 64 values
__global__ __launch_bounds__(256)
void topk_softplus_kernel(const float* __restrict__ resonance,
                          float* __restrict__ weights,      // [N, 8]
                          float* __restrict__ idx_out,      // [N, 8] as float
                          int n_rows)
{
    int warp = (blockIdx.x * blockDim.x + threadIdx.x) >> 5;
    int lane = threadIdx.x & 31;
    if (warp >= n_rows) return;

    const float* r = resonance + (size_t)warp * E_DIM;
    float v0 = r[lane];
    float v1 = r[lane + 32];

#pragma unroll
    for (int it = 0; it < TOPK; it++) {
        // local best of this lane's two slots
        float bv; int bi;
        if (v0 > v1 || (v0 == v1 && lane < lane + 32)) { bv = v0; bi = lane; }
        else                                            { bv = v1; bi = lane + 32; }
        // butterfly argmax (tie -> smaller index)
#pragma unroll
        for (int off = 16; off > 0; off >>= 1) {
            float ov = __shfl_xor_sync(0xffffffffu, bv, off);
            int   oi = __shfl_xor_sync(0xffffffffu, bi, off);
            if (ov > bv || (ov == bv && oi < bi)) { bv = ov; bi = oi; }
        }
        if (lane == 0) {
            weights[(size_t)warp * TOPK + it] = softplus_f(bv);
            idx_out[(size_t)warp * TOPK + it] = (float)bi;
        }
        // owner removes the winner
        if (bi == lane)      v0 = -INFINITY;
        if (bi == lane + 32) v1 = -INFINITY;
    }
}

extern "C" void kernel_launch(void* const* d_in, const int* in_sizes, int n_in,
                              void* d_out, int out_size)
{
    const float* x   = (const float*)d_in[0];
    const float* sig = (const float*)d_in[1];
    int n_rows = in_sizes[0] / D_DIM;       // 16384

    float* out = (float*)d_out;
    float* weights   = out;                         // [N,8]
    float* idx_out   = out + (size_t)n_rows * TOPK; // [N,8]
    float* resonance = out + (size_t)n_rows * TOPK * 2; // [N,64]

    dim3 g1(n_rows / BM);
    router_gemm_kernel<<<g1, 256>>>(x, sig, resonance, n_rows);

    int warps_per_block = 256 / 32;
    dim3 g2((n_rows + warps_per_block - 1) / warps_per_block);
    topk_softplus_kernel<<<g2, 256>>>(resonance, weights, idx_out, n_rows);
}